// round 5
// baseline (speedup 1.0000x reference)
#include <cuda_runtime.h>
#include <cstdint>

// Conv2d N=32, Cin=64, 64x64, Cout=128, 3x3 s1 p1, fp32.
// Implicit GEMM on mma.sync.m16n8k8.tf32.
// R5: 32 warps (1024 thr), warp tile 32x32, A stored as (k,k+4) pairs so
// a-frag halves load with LDS.64 (conflict-free: pair stride 808 = 8 mod 32).
//
// CTA: one n, 4 output rows -> M=256 (4y x 64x), N=128, K=576.
// SMEM: B 9 taps pre-paired (144 x 264 floats) + A pairs (16 x 808 floats).

#define HW  64
#define CO  128
#define CIN 64

#define SB_ROW    264
#define SB_FLOATS (144 * SB_ROW)          // 38016
#define SA_OFF    SB_FLOATS
#define PS        808                     // pair stride: 6*66*2=792 data, 8 mod 32
#define SMEM_BYTES ((SB_FLOATS + 16 * PS) * 4)   // 203,776 B

__device__ __forceinline__ uint32_t f2tf32(float f) {
    uint32_t r; asm("cvt.rna.tf32.f32 %0, %1;" : "=r"(r) : "f"(f)); return r;
}
__device__ __forceinline__ void mma8(float c[4], uint2 a0, uint2 a1, uint2 b) {
    // a0 = {A[m,k], A[m,k+4]}, a1 = {A[m+8,k], A[m+8,k+4]}
    asm volatile(
        "mma.sync.aligned.m16n8k8.row.col.f32.tf32.tf32.f32 "
        "{%0,%1,%2,%3}, {%4,%5,%6,%7}, {%8,%9}, {%0,%1,%2,%3};"
        : "+f"(c[0]), "+f"(c[1]), "+f"(c[2]), "+f"(c[3])
        : "r"(a0.x), "r"(a1.x), "r"(a0.y), "r"(a1.y), "r"(b.x), "r"(b.y));
}

__global__ void __launch_bounds__(1024, 1)
conv_mma_kernel(const float* __restrict__ in, const float* __restrict__ w,
                const float* __restrict__ bias, float* __restrict__ out)
{
    extern __shared__ float sm[];

    const int tid    = threadIdx.x;
    const int lane   = tid & 31;
    const int warp   = tid >> 5;
    const int warpM  = warp >> 2;       // 0..7
    const int warpN  = warp & 3;        // 0..3 -> co 32-block
    const int ylocal = warpM >> 1;      // 0..3
    const int xhalf  = (warpM & 1) * 32;
    const int y0     = blockIdx.x * 4;
    const int n      = blockIdx.y;

    const int r = lane >> 2;            // 0..7
    const int j = lane & 3;             // 0..3

    float acc[2][4][4];
#pragma unroll
    for (int mt = 0; mt < 2; ++mt)
#pragma unroll
        for (int nt = 0; nt < 4; ++nt)
#pragma unroll
            for (int q = 0; q < 4; ++q) acc[mt][nt][q] = 0.f;

    for (int chunk = 0; chunk < 2; ++chunk) {
        const int cib = chunk * 32;
        __syncthreads();   // previous chunk's LDS reads complete

        // ---- stage A: (k,k+4) pairs; addr = pair*PS + (row*66+col)*2 + slot ----
        const float* inb = in + ((size_t)n * CIN + cib) * (HW * HW);
        for (int e = tid; e < 32 * 396; e += 1024) {
            int p   = e / 66;           // ci*6 + row
            int col = e - p * 66;
            int ci  = p / 6;
            int row = p - ci * 6;
            int gy  = y0 - 1 + row;
            int gx  = col - 1;
            float v = 0.f;
            if ((unsigned)gy < (unsigned)HW && (unsigned)gx < (unsigned)HW)
                v = inb[((size_t)ci * HW + gy) * HW + gx];
            int s    = ci >> 3;
            int rem  = ci & 7;
            int pair = s * 4 + (rem & 3);
            int slot = rem >> 2;
            sm[SA_OFF + pair * PS + (row * 66 + col) * 2 + slot] =
                __uint_as_float(f2tf32(v));
        }

        // ---- stage B: rows (tap, s, j) hold pairs (k, k+4) per co ----
        const float* wb = w + (size_t)cib * 9 * CO;
        for (int e = tid; e < 144 * 128; e += 1024) {
            int co   = e & 127;
            int rowp = e >> 7;              // 0..143
            int tap  = rowp >> 4;
            int s    = (rowp >> 2) & 3;
            int jj   = rowp & 3;
            int k    = s * 8 + jj;
            float2 pv;
            pv.x = __uint_as_float(f2tf32(wb[((size_t)k * 9 + tap) * CO + co]));
            pv.y = __uint_as_float(f2tf32(wb[((size_t)(k + 4) * 9 + tap) * CO + co]));
            *(float2*)&sm[rowp * SB_ROW + 2 * co] = pv;
        }
        __syncthreads();

        // ---- compute: 9 taps x 4 ksteps, warp tile 32x32 ----
#pragma unroll
        for (int tap = 0; tap < 9; ++tap) {
            const int dy = tap / 3 - 1;
            const int dx = tap % 3 - 1;
            const float* pA = &sm[SA_OFF + j * PS
                                  + ((ylocal + dy + 1) * 66 + 1 + dx + xhalf + r) * 2];
            const float* pB = &sm[(tap * 16 + j) * SB_ROW + 2 * (warpN * 32 + r)];
#pragma unroll
            for (int s = 0; s < 4; ++s) {
                const float* pAs = pA + s * 4 * PS;
                uint2 a00 = *(const uint2*)(pAs);        // m = r      : {k, k+4}
                uint2 a01 = *(const uint2*)(pAs + 16);   // m = r + 8
                uint2 a10 = *(const uint2*)(pAs + 32);   // m = 16 + r
                uint2 a11 = *(const uint2*)(pAs + 48);   // m = 24 + r
                const float* pBs = pB + s * 4 * SB_ROW;
#pragma unroll
                for (int nt = 0; nt < 4; ++nt) {
                    uint2 b = *(const uint2*)&pBs[nt * 16];
                    mma8(acc[0][nt], a00, a01, b);
                    mma8(acc[1][nt], a10, a11, b);
                }
            }
        }
    }

    // ---- epilogue: c frag rows (r, r+8), cols (2j, 2j+1) ----
    const int y = y0 + ylocal;
#pragma unroll
    for (int nt = 0; nt < 4; ++nt) {
        int co = warpN * 32 + nt * 8 + 2 * j;
        float b0 = __ldg(bias + co);
        float b1 = __ldg(bias + co + 1);
        float* o0 = out + (((size_t)n * CO + co) * HW + y) * HW + xhalf;
#pragma unroll
        for (int mt = 0; mt < 2; ++mt) {
            int x = mt * 16 + r;
            o0[x]               = acc[mt][nt][0] + b0;
            o0[HW * HW + x]     = acc[mt][nt][1] + b1;
            o0[x + 8]           = acc[mt][nt][2] + b0;
            o0[HW * HW + x + 8] = acc[mt][nt][3] + b1;
        }
    }
}

extern "C" void kernel_launch(void* const* d_in, const int* in_sizes, int n_in,
                              void* d_out, int out_size)
{
    const float* in   = (const float*)d_in[0];
    const float* w    = (const float*)d_in[1];
    const float* bias = (const float*)d_in[2];
    float* out        = (float*)d_out;

    cudaFuncSetAttribute(conv_mma_kernel,
                         cudaFuncAttributeMaxDynamicSharedMemorySize, SMEM_BYTES);
    dim3 grid(16, 32);
    conv_mma_kernel<<<grid, 1024, SMEM_BYTES>>>(in, w, bias, out);
}